// round 14
// baseline (speedup 1.0000x reference)
#include <cuda_runtime.h>
#include <cuda_bf16.h>
#include <cuda_fp16.h>
#include <cstdint>

// ---------------------------------------------------------------------------
// VariationalEncoder (3-layer GCN VGAE), N=100000, E=1600000, 512->128->{64,64}
// R14 (from R13 @ 397.8us, GEMM1 134us tensor=55% issue=19.9%):
//  * GEMM: double-buffered BK=32 + ldmatrix (the combo R11/R13 never had) --
//    cp.async latency hidden behind previous stage's MMAs; pitch 40 is
//    ldmatrix conflict-free (row stride 80B -> bank r*5 mod 8, 5 coprime 8).
//    80KB smem, 2 CTA/SM, 64-reg cap.
//  * aggs: edge unroll 2 -> 4 (latency-bound per R10 evidence; MLP 4).
// ---------------------------------------------------------------------------

#define N_NODES 100000
#define N_EDGES 1600000
#define C_IN    512
#define C_HID   128
#define NB1     ((N_NODES + 1023) / 1024)

// -------------------- device scratch ---------------------------------------
__device__ int    g_is64;
__device__ int    g_deg[N_NODES];
__device__ float  g_dinv[N_NODES];
__device__ int    g_rowstart[N_NODES + 1];
__device__ int    g_cursor[N_NODES];
__device__ int    g_bsum[NB1];
__device__ int    g_boff[NB1 + 1];
__device__ int    g_csr[N_EDGES];
__device__ __nv_bfloat16 g_xhi[(size_t)N_NODES * C_IN];
__device__ __nv_bfloat16 g_xlo[(size_t)N_NODES * C_IN];
__device__ __nv_bfloat16 g_w1thi[C_HID * C_IN];   // [n][k] transposed
__device__ __nv_bfloat16 g_w1tlo[C_HID * C_IN];
__device__ __nv_bfloat16 g_wcthi[C_HID * C_HID];  // [n][k], n = [mu|ls]
__device__ __nv_bfloat16 g_wctlo[C_HID * C_HID];
__device__ __nv_bfloat16 g_hhi[(size_t)N_NODES * C_HID];
__device__ __nv_bfloat16 g_hlo[(size_t)N_NODES * C_HID];
__device__ __half g_t1h[(size_t)N_NODES * C_HID];   // fp16 gather tables
__device__ __half g_t2h[(size_t)N_NODES * C_HID];

// -------------------- helpers ----------------------------------------------
__device__ __forceinline__ void splitf(float x, __nv_bfloat16& hi,
                                       __nv_bfloat16& lo) {
    hi = __float2bfloat16_rn(x);
    lo = __float2bfloat16_rn(x - __bfloat162float(hi));
}
__device__ __forceinline__ unsigned pack2(__nv_bfloat16 a, __nv_bfloat16 b) {
    return (unsigned)__bfloat16_as_ushort(a) |
           ((unsigned)__bfloat16_as_ushort(b) << 16);
}

// -------------------- dtype detection --------------------------------------
__global__ void k_detect(const unsigned int* __restrict__ w) {
    bool is64 = true;
    #pragma unroll
    for (int i = 0; i < 8; i++)
        if (w[2 * i + 1] != 0u) is64 = false;
    g_is64 = is64 ? 1 : 0;
}

__device__ __forceinline__ int edge_at(const void* __restrict__ ei,
                                       int row, int e) {
    if (g_is64)
        return (int)((const long long*)ei)[(size_t)row * N_EDGES + e];
    return ((const int*)ei)[(size_t)row * N_EDGES + e];
}

// -------------------- splits -----------------------------------------------
__global__ void k_splitx(const float4* __restrict__ x) {
    size_t i = (size_t)blockIdx.x * blockDim.x + threadIdx.x;   // float4 idx
    if (i >= (size_t)N_NODES * C_IN / 4) return;
    float4 v = x[i];
    __nv_bfloat16 h0, l0, h1, l1, h2, l2, h3, l3;
    splitf(v.x, h0, l0); splitf(v.y, h1, l1);
    splitf(v.z, h2, l2); splitf(v.w, h3, l3);
    *(uint2*)&g_xhi[i * 4] = make_uint2(pack2(h0, h1), pack2(h2, h3));
    *(uint2*)&g_xlo[i * 4] = make_uint2(pack2(l0, l1), pack2(l2, l3));
}

__global__ void k_splitw1(const float* __restrict__ W1) {
    int i = blockIdx.x * blockDim.x + threadIdx.x;   // over 512*128
    if (i >= C_IN * C_HID) return;
    int k = i >> 7, n = i & 127;
    __nv_bfloat16 h, l;
    splitf(W1[i], h, l);
    g_w1thi[n * C_IN + k] = h;
    g_w1tlo[n * C_IN + k] = l;
}

__global__ void k_packwt(const float* __restrict__ Wmu,
                         const float* __restrict__ Wls) {
    int i = blockIdx.x * blockDim.x + threadIdx.x;   // over 128*128
    if (i >= C_HID * C_HID) return;
    int k = i >> 7, n = i & 127;
    float w = (n < 64) ? Wmu[k * 64 + n] : Wls[k * 64 + (n - 64)];
    __nv_bfloat16 h, l;
    splitf(w, h, l);
    g_wcthi[n * C_HID + k] = h;
    g_wctlo[n * C_HID + k] = l;
}

// -------------------- graph preprocessing ----------------------------------
__global__ void k_set_deg(void) {
    int i = blockIdx.x * blockDim.x + threadIdx.x;
    if (i < N_NODES) g_deg[i] = 1;
}

__global__ void k_count(const void* __restrict__ ei) {
    int e = blockIdx.x * blockDim.x + threadIdx.x;
    if (e < N_EDGES) {
        int d = edge_at(ei, 1, e);
        if (d >= 0 && d < N_NODES) atomicAdd(&g_deg[d], 1);
    }
}

__global__ void __launch_bounds__(1024) k_scan1(void) {
    int tid  = threadIdx.x;
    int idx  = blockIdx.x * 1024 + tid;
    int lane = tid & 31, wid = tid >> 5;
    int deg = (idx < N_NODES) ? g_deg[idx] : 1;
    int v   = (idx < N_NODES) ? (deg - 1) : 0;
    if (idx < N_NODES) g_dinv[idx] = rsqrtf((float)deg);
    int incl = v;
    #pragma unroll
    for (int off = 1; off < 32; off <<= 1) {
        int t = __shfl_up_sync(0xffffffffu, incl, off);
        if (lane >= off) incl += t;
    }
    __shared__ int wsum[32];
    if (lane == 31) wsum[wid] = incl;
    __syncthreads();
    if (wid == 0) {
        int s = wsum[lane];
        #pragma unroll
        for (int off = 1; off < 32; off <<= 1) {
            int t = __shfl_up_sync(0xffffffffu, s, off);
            if (lane >= off) s += t;
        }
        wsum[lane] = s;
    }
    __syncthreads();
    int woff = (wid > 0) ? wsum[wid - 1] : 0;
    int excl = woff + incl - v;
    if (idx < N_NODES) g_rowstart[idx] = excl;
    if (tid == 1023) g_bsum[blockIdx.x] = woff + incl;
}

__global__ void k_scan2(void) {
    __shared__ int s[128];
    int tid = threadIdx.x;
    int v = (tid < NB1) ? g_bsum[tid] : 0;
    s[tid] = v;
    __syncthreads();
    #pragma unroll
    for (int off = 1; off < 128; off <<= 1) {
        int t = (tid >= off) ? s[tid - off] : 0;
        __syncthreads();
        s[tid] += t;
        __syncthreads();
    }
    int incl = s[tid];
    if (tid < NB1) g_boff[tid] = incl - v;
    if (tid == NB1 - 1) g_boff[NB1] = incl;
}

__global__ void k_scan3(void) {
    int idx = blockIdx.x * blockDim.x + threadIdx.x;
    if (idx < N_NODES) {
        int r = g_rowstart[idx] + g_boff[idx >> 10];
        g_rowstart[idx] = r;
        g_cursor[idx]   = r;
    }
    if (idx == 0) g_rowstart[N_NODES] = g_boff[NB1];
}

__global__ void k_scatter(const void* __restrict__ ei) {
    int e = blockIdx.x * blockDim.x + threadIdx.x;
    if (e < N_EDGES) {
        int sidx = edge_at(ei, 0, e);
        int d    = edge_at(ei, 1, e);
        if (d >= 0 && d < N_NODES && sidx >= 0 && sidx < N_NODES) {
            int pos = atomicAdd(&g_cursor[d], 1);
            if (pos >= 0 && pos < N_EDGES) g_csr[pos] = sidx;
        }
    }
}

// -------------------- HMMA GEMM: ldmatrix + double buffer ------------------
// C[M,128] (fp16) = (Ahi+Alo)[M,K] @ (Bthi+Btlo)[128,K]^T  (3-term split)
// 512 thr, 2 CTA/SM, BK=32, 2-stage cp.async pipeline, ldmatrix.x4 frags.
#define GP      40                    // bf16 pitch (80 B); r*5 mod 8 banks
#define TILE_E  (128 * GP)            // 5120 elems = 10240 B per array
#define SMEM_BYTES (2 * 4 * TILE_E * 2)   // 81920 B

__device__ __forceinline__ void mma_bf16(float* c, const unsigned* a,
                                         const unsigned* b) {
    asm volatile(
        "mma.sync.aligned.m16n8k16.row.col.f32.bf16.bf16.f32 "
        "{%0,%1,%2,%3}, {%4,%5,%6,%7}, {%8,%9}, {%0,%1,%2,%3};"
        : "+f"(c[0]), "+f"(c[1]), "+f"(c[2]), "+f"(c[3])
        : "r"(a[0]), "r"(a[1]), "r"(a[2]), "r"(a[3]), "r"(b[0]), "r"(b[1]));
}

__device__ __forceinline__ void ldsm4(unsigned* r, unsigned addr) {
    asm volatile(
        "ldmatrix.sync.aligned.m8n8.x4.shared.b16 {%0,%1,%2,%3}, [%4];"
        : "=r"(r[0]), "=r"(r[1]), "=r"(r[2]), "=r"(r[3]) : "r"(addr));
}

__device__ __forceinline__ void cp16(unsigned s, const void* g) {
    asm volatile("cp.async.cg.shared.global [%0], [%1], 16;\n"
                 :: "r"(s), "l"(g));
}

__global__ void __launch_bounds__(512, 2)
k_gemm(const __nv_bfloat16* __restrict__ Ahi,
       const __nv_bfloat16* __restrict__ Alo,
       const __nv_bfloat16* __restrict__ Bthi,   // [128][K]
       const __nv_bfloat16* __restrict__ Btlo,
       __half* __restrict__ C, int M, int K) {
    extern __shared__ __nv_bfloat16 sm[];
    unsigned smbase = (unsigned)__cvta_generic_to_shared(sm);

    int tid   = threadIdx.x;
    int lane  = tid & 31;
    int wid   = tid >> 5;
    int warpM = wid >> 2;            // 0..3 -> m * 32
    int warpN = wid & 3;             // 0..3 -> n * 32
    int m0    = blockIdx.x * 128;
    int S     = K / 32;

    const __nv_bfloat16* gsrc[4] = {Ahi, Alo, Bthi, Btlo};

    float acc[2][4][4];
    #pragma unroll
    for (int i = 0; i < 2; i++)
        #pragma unroll
        for (int j = 0; j < 4; j++)
            #pragma unroll
            for (int r = 0; r < 4; r++) acc[i][j][r] = 0.f;

    int lj = lane >> 3;              // 0..3 (ldmatrix sub-tile index)
    int ri = lane & 7;

    // stage s -> buffer s&1; 4 arr x 128 rows x 32 bf16 = 2048 chunks, 4/thr
    auto issue = [&](int s) {
        int buf = s & 1;
        int k0  = s * 32;
        #pragma unroll
        for (int i = 0; i < 4; i++) {
            int c   = i * 512 + tid;          // 0..2047
            int arr = c >> 9;                 // 0..3
            int rem = c & 511;
            int row = rem >> 2;
            int c16 = rem & 3;
            int gr;
            if (arr < 2) { gr = m0 + row; if (gr >= M) gr = 0; }
            else         { gr = row; }
            const __nv_bfloat16* g = gsrc[arr] + (size_t)gr * K + k0 + c16 * 8;
            unsigned d = smbase +
                (unsigned)((buf * 4 + arr) * TILE_E + row * GP + c16 * 8) * 2;
            cp16(d, g);
        }
        asm volatile("cp.async.commit_group;\n");
    };

    issue(0);
    for (int s = 0; s < S; s++) {
        if (s + 1 < S) {
            issue(s + 1);
            asm volatile("cp.async.wait_group 1;\n");
        } else {
            asm volatile("cp.async.wait_group 0;\n");
        }
        __syncthreads();

        int buf = s & 1;
        unsigned bAhi = smbase + (unsigned)(buf * 4 + 0) * TILE_E * 2;
        unsigned bAlo = smbase + (unsigned)(buf * 4 + 1) * TILE_E * 2;
        unsigned bBhi = smbase + (unsigned)(buf * 4 + 2) * TILE_E * 2;
        unsigned bBlo = smbase + (unsigned)(buf * 4 + 3) * TILE_E * 2;

        #pragma unroll
        for (int k16 = 0; k16 < 2; k16++) {
            int kc = k16 * 16;
            // B frags: x4 covers (in, khalf): in = lj>>1, h = lj&1
            unsigned bhi[8], blo[8];
            {
                int in0 = lj >> 1, h0 = lj & 1;
                unsigned off0 = (unsigned)((warpN * 32 + in0 * 8 + ri) * GP
                                           + kc + h0 * 8) * 2;
                unsigned off1 = (unsigned)((warpN * 32 + 16 + in0 * 8 + ri) * GP
                                           + kc + h0 * 8) * 2;
                ldsm4(bhi,     bBhi + off0);
                ldsm4(bhi + 4, bBhi + off1);
                ldsm4(blo,     bBlo + off0);
                ldsm4(blo + 4, bBlo + off1);
            }
            #pragma unroll
            for (int im = 0; im < 2; im++) {
                int r0 = warpM * 32 + im * 16;
                unsigned aoff = (unsigned)((r0 + (lj & 1) * 8 + ri) * GP
                                           + kc + (lj >> 1) * 8) * 2;
                unsigned ahi[4], alo[4];
                ldsm4(ahi, bAhi + aoff);
                ldsm4(alo, bAlo + aoff);
                #pragma unroll
                for (int in = 0; in < 4; in++) {
                    mma_bf16(acc[im][in], ahi, &bhi[in * 2]);
                    mma_bf16(acc[im][in], ahi, &blo[in * 2]);
                    mma_bf16(acc[im][in], alo, &bhi[in * 2]);
                }
            }
        }
        __syncthreads();   // protect buf before issue(s+2) overwrites it
    }

    #pragma unroll
    for (int im = 0; im < 2; im++) {
        int r = m0 + warpM * 32 + im * 16 + (lane >> 2);
        #pragma unroll
        for (int in = 0; in < 4; in++) {
            int c = warpN * 32 + in * 8 + (lane & 3) * 2;
            if (r < M)
                *(__half2*)&C[(size_t)r * 128 + c] =
                    __floats2half2_rn(acc[im][in][0], acc[im][in][1]);
            if (r + 8 < M)
                *(__half2*)&C[(size_t)(r + 8) * 128 + c] =
                    __floats2half2_rn(acc[im][in][2], acc[im][in][3]);
        }
    }
}

// -------------------- aggregation (fp16 tables, MLP=4) ---------------------
__device__ __forceinline__ float4 agg_node_h(const __half* __restrict__ t,
                                             int d, int lane) {
    float dv = g_dinv[d];
    size_t ch = lane * 4;
    uint2 uv = *(const uint2*)(t + (size_t)d * C_HID + ch);
    float2 v0 = __half22float2(*(__half2*)&uv.x);
    float2 v1 = __half22float2(*(__half2*)&uv.y);
    float w = dv * dv;
    float4 acc = make_float4(w * v0.x, w * v0.y, w * v1.x, w * v1.y);
    int beg = g_rowstart[d], end = g_rowstart[d + 1];
    int i = beg;
    for (; i + 3 < end; i += 4) {      // 4-wide: all gathers before FMAs
        int s0 = g_csr[i],     s1 = g_csr[i + 1];
        int s2 = g_csr[i + 2], s3 = g_csr[i + 3];
        float w0 = dv * g_dinv[s0];
        float w1 = dv * g_dinv[s1];
        float w2 = dv * g_dinv[s2];
        float w3 = dv * g_dinv[s3];
        uint2 a = __ldg((const uint2*)(t + (size_t)s0 * C_HID + ch));
        uint2 b = __ldg((const uint2*)(t + (size_t)s1 * C_HID + ch));
        uint2 c = __ldg((const uint2*)(t + (size_t)s2 * C_HID + ch));
        uint2 e = __ldg((const uint2*)(t + (size_t)s3 * C_HID + ch));
        float2 a0 = __half22float2(*(__half2*)&a.x);
        float2 a1 = __half22float2(*(__half2*)&a.y);
        float2 b0 = __half22float2(*(__half2*)&b.x);
        float2 b1 = __half22float2(*(__half2*)&b.y);
        float2 c0 = __half22float2(*(__half2*)&c.x);
        float2 c1 = __half22float2(*(__half2*)&c.y);
        float2 e0 = __half22float2(*(__half2*)&e.x);
        float2 e1 = __half22float2(*(__half2*)&e.y);
        acc.x += w0 * a0.x + w1 * b0.x + w2 * c0.x + w3 * e0.x;
        acc.y += w0 * a0.y + w1 * b0.y + w2 * c0.y + w3 * e0.y;
        acc.z += w0 * a1.x + w1 * b1.x + w2 * c1.x + w3 * e1.x;
        acc.w += w0 * a1.y + w1 * b1.y + w2 * c1.y + w3 * e1.y;
    }
    for (; i < end; i++) {
        int s0 = g_csr[i];
        float w0 = dv * g_dinv[s0];
        uint2 a = __ldg((const uint2*)(t + (size_t)s0 * C_HID + ch));
        float2 a0 = __half22float2(*(__half2*)&a.x);
        float2 a1 = __half22float2(*(__half2*)&a.y);
        acc.x += w0 * a0.x; acc.y += w0 * a0.y;
        acc.z += w0 * a1.x; acc.w += w0 * a1.y;
    }
    return acc;
}

// h = relu(A_hat t1 + b1) emitted as (hi, lo) bf16 pair for GEMM2.
__global__ void __launch_bounds__(256)
k_agg1(const float* __restrict__ b1) {
    int gw = (blockIdx.x * blockDim.x + threadIdx.x) >> 5;
    if (gw >= N_NODES) return;
    int lane = threadIdx.x & 31;
    float4 acc = agg_node_h(g_t1h, gw, lane);
    float4 bb = *(const float4*)&b1[lane * 4];
    acc.x = fmaxf(acc.x + bb.x, 0.f);
    acc.y = fmaxf(acc.y + bb.y, 0.f);
    acc.z = fmaxf(acc.z + bb.z, 0.f);
    acc.w = fmaxf(acc.w + bb.w, 0.f);
    __nv_bfloat16 h0, l0, h1, l1, h2, l2, h3, l3;
    splitf(acc.x, h0, l0); splitf(acc.y, h1, l1);
    splitf(acc.z, h2, l2); splitf(acc.w, h3, l3);
    size_t o = (size_t)gw * C_HID + lane * 4;
    *(uint2*)&g_hhi[o] = make_uint2(pack2(h0, h1), pack2(h2, h3));
    *(uint2*)&g_hlo[o] = make_uint2(pack2(l0, l1), pack2(l2, l3));
}

__global__ void __launch_bounds__(256)
k_agg2(const float* __restrict__ b_mu, const float* __restrict__ b_ls,
       float* __restrict__ out) {
    int gw = (blockIdx.x * blockDim.x + threadIdx.x) >> 5;
    if (gw >= N_NODES) return;
    int lane = threadIdx.x & 31;
    float4 acc = agg_node_h(g_t2h, gw, lane);
    int c = lane * 4;
    if (c < 64) {
        float4 bb = *(const float4*)&b_mu[c];
        acc.x += bb.x; acc.y += bb.y; acc.z += bb.z; acc.w += bb.w;
        *(float4*)&out[(size_t)gw * 64 + c] = acc;
    } else {
        float4 bb = *(const float4*)&b_ls[c - 64];
        acc.x += bb.x; acc.y += bb.y; acc.z += bb.z; acc.w += bb.w;
        *(float4*)&out[(size_t)N_NODES * 64 + (size_t)gw * 64 + (c - 64)] = acc;
    }
}

// -------------------- launch -----------------------------------------------
extern "C" void kernel_launch(void* const* d_in, const int* in_sizes, int n_in,
                              void* d_out, int out_size) {
    const float* x    = (const float*)d_in[0];
    const void*  ei   = d_in[1];
    const float* W1   = (const float*)d_in[2];
    const float* b1   = (const float*)d_in[3];
    const float* Wmu  = (const float*)d_in[4];
    const float* bmu  = (const float*)d_in[5];
    const float* Wls  = (const float*)d_in[6];
    const float* bls  = (const float*)d_in[7];
    float*       out  = (float*)d_out;

    (void)in_sizes; (void)n_in; (void)out_size;

    void *p_xhi, *p_xlo, *p_w1thi, *p_w1tlo, *p_wcthi, *p_wctlo;
    void *p_hhi, *p_hlo, *p_t1h, *p_t2h;
    cudaGetSymbolAddress(&p_xhi,   g_xhi);
    cudaGetSymbolAddress(&p_xlo,   g_xlo);
    cudaGetSymbolAddress(&p_w1thi, g_w1thi);
    cudaGetSymbolAddress(&p_w1tlo, g_w1tlo);
    cudaGetSymbolAddress(&p_wcthi, g_wcthi);
    cudaGetSymbolAddress(&p_wctlo, g_wctlo);
    cudaGetSymbolAddress(&p_hhi,   g_hhi);
    cudaGetSymbolAddress(&p_hlo,   g_hlo);
    cudaGetSymbolAddress(&p_t1h,   g_t1h);
    cudaGetSymbolAddress(&p_t2h,   g_t2h);

    cudaFuncSetAttribute(k_gemm,
        cudaFuncAttributeMaxDynamicSharedMemorySize, SMEM_BYTES);

    int nblk = (N_NODES + 127) / 128;

    // inputs -> split operands (no graph dependency)
    k_detect <<<1, 1>>>((const unsigned int*)ei);
    k_splitx <<<(N_NODES * (C_IN / 4) + 255) / 256, 256>>>((const float4*)x);
    k_splitw1<<<(C_IN * C_HID + 255) / 256, 256>>>(W1);

    // GEMM1 (ncu capture slot)
    k_gemm<<<nblk, 512, SMEM_BYTES>>>(
        (const __nv_bfloat16*)p_xhi, (const __nv_bfloat16*)p_xlo,
        (const __nv_bfloat16*)p_w1thi, (const __nv_bfloat16*)p_w1tlo,
        (__half*)p_t1h, N_NODES, C_IN);

    // graph preprocessing
    k_set_deg<<<(N_NODES + 255) / 256, 256>>>();
    k_count  <<<(N_EDGES + 255) / 256, 256>>>(ei);
    k_scan1  <<<NB1, 1024>>>();
    k_scan2  <<<1, 128>>>();
    k_scan3  <<<(N_NODES + 255) / 256, 256>>>();
    k_scatter<<<(N_EDGES + 255) / 256, 256>>>(ei);

    // layer 1 aggregate (emits split h)
    k_agg1<<<(N_NODES * 32 + 255) / 256, 256>>>(b1);

    // layers 2+3 fused
    k_packwt<<<(C_HID * C_HID + 255) / 256, 256>>>(Wmu, Wls);
    k_gemm<<<nblk, 512, SMEM_BYTES>>>(
        (const __nv_bfloat16*)p_hhi, (const __nv_bfloat16*)p_hlo,
        (const __nv_bfloat16*)p_wcthi, (const __nv_bfloat16*)p_wctlo,
        (__half*)p_t2h, N_NODES, C_HID);
    k_agg2<<<(N_NODES * 32 + 255) / 256, 256>>>(bmu, bls, out);
}

// round 15
// speedup vs baseline: 1.2134x; 1.2134x over previous
#include <cuda_runtime.h>
#include <cuda_bf16.h>
#include <cuda_fp16.h>
#include <cstdint>

// ---------------------------------------------------------------------------
// VariationalEncoder (3-layer GCN VGAE), N=100000, E=1600000, 512->128->{64,64}
// R15 (from R13 @ 397.8us; R14's dbl-buffer + agg-MLP4 both neutral/negative,
// reverted): GEMM core = R13 (single-buffer BK=64 + ldmatrix, 134us).
// Structural change: k_splitx ELIMINATED -- GEMM1 loads x fp32 directly
// (LDG.128) and splits to bf16 hi/lo during the smem fill (~3 ALU/elt,
// STS.64), saving ~410MB of DRAM round-trip (~55-60us) for ~+25us in GEMM1.
// GEMM2 keeps the pre-split path (h is emitted split by agg1 for free).
// ---------------------------------------------------------------------------

#define N_NODES 100000
#define N_EDGES 1600000
#define C_IN    512
#define C_HID   128
#define NB1     ((N_NODES + 1023) / 1024)

// -------------------- device scratch ---------------------------------------
__device__ int    g_is64;
__device__ int    g_deg[N_NODES];
__device__ float  g_dinv[N_NODES];
__device__ int    g_rowstart[N_NODES + 1];
__device__ int    g_cursor[N_NODES];
__device__ int    g_bsum[NB1];
__device__ int    g_boff[NB1 + 1];
__device__ int    g_csr[N_EDGES];
__device__ __nv_bfloat16 g_w1thi[C_HID * C_IN];   // [n][k] transposed
__device__ __nv_bfloat16 g_w1tlo[C_HID * C_IN];
__device__ __nv_bfloat16 g_wcthi[C_HID * C_HID];  // [n][k], n = [mu|ls]
__device__ __nv_bfloat16 g_wctlo[C_HID * C_HID];
__device__ __nv_bfloat16 g_hhi[(size_t)N_NODES * C_HID];
__device__ __nv_bfloat16 g_hlo[(size_t)N_NODES * C_HID];
__device__ __half g_t1h[(size_t)N_NODES * C_HID];   // fp16 gather tables
__device__ __half g_t2h[(size_t)N_NODES * C_HID];

// -------------------- helpers ----------------------------------------------
__device__ __forceinline__ void splitf(float x, __nv_bfloat16& hi,
                                       __nv_bfloat16& lo) {
    hi = __float2bfloat16_rn(x);
    lo = __float2bfloat16_rn(x - __bfloat162float(hi));
}
__device__ __forceinline__ unsigned pack2(__nv_bfloat16 a, __nv_bfloat16 b) {
    return (unsigned)__bfloat16_as_ushort(a) |
           ((unsigned)__bfloat16_as_ushort(b) << 16);
}

// -------------------- dtype detection --------------------------------------
__global__ void k_detect(const unsigned int* __restrict__ w) {
    bool is64 = true;
    #pragma unroll
    for (int i = 0; i < 8; i++)
        if (w[2 * i + 1] != 0u) is64 = false;
    g_is64 = is64 ? 1 : 0;
}

__device__ __forceinline__ int edge_at(const void* __restrict__ ei,
                                       int row, int e) {
    if (g_is64)
        return (int)((const long long*)ei)[(size_t)row * N_EDGES + e];
    return ((const int*)ei)[(size_t)row * N_EDGES + e];
}

// -------------------- weight splits ----------------------------------------
__global__ void k_splitw1(const float* __restrict__ W1) {
    int i = blockIdx.x * blockDim.x + threadIdx.x;   // over 512*128
    if (i >= C_IN * C_HID) return;
    int k = i >> 7, n = i & 127;
    __nv_bfloat16 h, l;
    splitf(W1[i], h, l);
    g_w1thi[n * C_IN + k] = h;
    g_w1tlo[n * C_IN + k] = l;
}

__global__ void k_packwt(const float* __restrict__ Wmu,
                         const float* __restrict__ Wls) {
    int i = blockIdx.x * blockDim.x + threadIdx.x;   // over 128*128
    if (i >= C_HID * C_HID) return;
    int k = i >> 7, n = i & 127;
    float w = (n < 64) ? Wmu[k * 64 + n] : Wls[k * 64 + (n - 64)];
    __nv_bfloat16 h, l;
    splitf(w, h, l);
    g_wcthi[n * C_HID + k] = h;
    g_wctlo[n * C_HID + k] = l;
}

// -------------------- graph preprocessing ----------------------------------
__global__ void k_set_deg(void) {
    int i = blockIdx.x * blockDim.x + threadIdx.x;
    if (i < N_NODES) g_deg[i] = 1;
}

__global__ void k_count(const void* __restrict__ ei) {
    int e = blockIdx.x * blockDim.x + threadIdx.x;
    if (e < N_EDGES) {
        int d = edge_at(ei, 1, e);
        if (d >= 0 && d < N_NODES) atomicAdd(&g_deg[d], 1);
    }
}

__global__ void __launch_bounds__(1024) k_scan1(void) {
    int tid  = threadIdx.x;
    int idx  = blockIdx.x * 1024 + tid;
    int lane = tid & 31, wid = tid >> 5;
    int deg = (idx < N_NODES) ? g_deg[idx] : 1;
    int v   = (idx < N_NODES) ? (deg - 1) : 0;
    if (idx < N_NODES) g_dinv[idx] = rsqrtf((float)deg);
    int incl = v;
    #pragma unroll
    for (int off = 1; off < 32; off <<= 1) {
        int t = __shfl_up_sync(0xffffffffu, incl, off);
        if (lane >= off) incl += t;
    }
    __shared__ int wsum[32];
    if (lane == 31) wsum[wid] = incl;
    __syncthreads();
    if (wid == 0) {
        int s = wsum[lane];
        #pragma unroll
        for (int off = 1; off < 32; off <<= 1) {
            int t = __shfl_up_sync(0xffffffffu, s, off);
            if (lane >= off) s += t;
        }
        wsum[lane] = s;
    }
    __syncthreads();
    int woff = (wid > 0) ? wsum[wid - 1] : 0;
    int excl = woff + incl - v;
    if (idx < N_NODES) g_rowstart[idx] = excl;
    if (tid == 1023) g_bsum[blockIdx.x] = woff + incl;
}

__global__ void k_scan2(void) {
    __shared__ int s[128];
    int tid = threadIdx.x;
    int v = (tid < NB1) ? g_bsum[tid] : 0;
    s[tid] = v;
    __syncthreads();
    #pragma unroll
    for (int off = 1; off < 128; off <<= 1) {
        int t = (tid >= off) ? s[tid - off] : 0;
        __syncthreads();
        s[tid] += t;
        __syncthreads();
    }
    int incl = s[tid];
    if (tid < NB1) g_boff[tid] = incl - v;
    if (tid == NB1 - 1) g_boff[NB1] = incl;
}

__global__ void k_scan3(void) {
    int idx = blockIdx.x * blockDim.x + threadIdx.x;
    if (idx < N_NODES) {
        int r = g_rowstart[idx] + g_boff[idx >> 10];
        g_rowstart[idx] = r;
        g_cursor[idx]   = r;
    }
    if (idx == 0) g_rowstart[N_NODES] = g_boff[NB1];
}

__global__ void k_scatter(const void* __restrict__ ei) {
    int e = blockIdx.x * blockDim.x + threadIdx.x;
    if (e < N_EDGES) {
        int sidx = edge_at(ei, 0, e);
        int d    = edge_at(ei, 1, e);
        if (d >= 0 && d < N_NODES && sidx >= 0 && sidx < N_NODES) {
            int pos = atomicAdd(&g_cursor[d], 1);
            if (pos >= 0 && pos < N_EDGES) g_csr[pos] = sidx;
        }
    }
}

// -------------------- HMMA GEMM (R13 core, optional fused A-split) ---------
// C[M,128] (fp16) = (Ahi+Alo)[M,K] @ (Bthi+Btlo)[128,K]^T  (3-term split)
// 512 thr, 2 CTA/SM, BK=64, single-buffer smem, ldmatrix.x4 frags.
// FUSEA: A supplied as fp32 (x); split to bf16 hi/lo during smem fill.
#define GP      72                    // bf16 pitch (144 B, conflict-free LDSM)
#define TILE_E  (128 * GP)            // 9216 elems = 18432 B per array
#define SMEM_BYTES (4 * TILE_E * 2)   // 73728 B

__device__ __forceinline__ void mma_bf16(float* c, const unsigned* a,
                                         const unsigned* b) {
    asm volatile(
        "mma.sync.aligned.m16n8k16.row.col.f32.bf16.bf16.f32 "
        "{%0,%1,%2,%3}, {%4,%5,%6,%7}, {%8,%9}, {%0,%1,%2,%3};"
        : "+f"(c[0]), "+f"(c[1]), "+f"(c[2]), "+f"(c[3])
        : "r"(a[0]), "r"(a[1]), "r"(a[2]), "r"(a[3]), "r"(b[0]), "r"(b[1]));
}

__device__ __forceinline__ void ldsm4(unsigned* r, unsigned addr) {
    asm volatile(
        "ldmatrix.sync.aligned.m8n8.x4.shared.b16 {%0,%1,%2,%3}, [%4];"
        : "=r"(r[0]), "=r"(r[1]), "=r"(r[2]), "=r"(r[3]) : "r"(addr));
}

__device__ __forceinline__ void cp16(unsigned s, const void* g) {
    asm volatile("cp.async.cg.shared.global [%0], [%1], 16;\n"
                 :: "r"(s), "l"(g));
}

template <bool FUSEA>
__global__ void __launch_bounds__(512, 2)
k_gemm(const float* __restrict__ Af,             // fp32 A (FUSEA only)
       const __nv_bfloat16* __restrict__ Ahi,    // pre-split A (else)
       const __nv_bfloat16* __restrict__ Alo,
       const __nv_bfloat16* __restrict__ Bthi,   // [128][K]
       const __nv_bfloat16* __restrict__ Btlo,
       __half* __restrict__ C, int M, int K) {
    extern __shared__ __nv_bfloat16 sm[];
    unsigned smbase = (unsigned)__cvta_generic_to_shared(sm);

    int tid   = threadIdx.x;
    int lane  = tid & 31;
    int wid   = tid >> 5;
    int warpM = wid >> 2;            // 0..3 -> m * 32
    int warpN = wid & 3;             // 0..3 -> n * 32
    int m0    = blockIdx.x * 128;
    int S     = K / 64;

    float acc[2][4][4];
    #pragma unroll
    for (int i = 0; i < 2; i++)
        #pragma unroll
        for (int j = 0; j < 4; j++)
            #pragma unroll
            for (int r = 0; r < 4; r++) acc[i][j][r] = 0.f;

    int lj = lane >> 3;              // ldmatrix sub-tile index
    int ri = lane & 7;

    for (int s = 0; s < S; s++) {
        int k0 = s * 64;
        if (FUSEA) {
            // B tiles via cp.async: 2 arrays x 128 rows x 8 chunks = 2048
            #pragma unroll
            for (int i = 0; i < 4; i++) {
                int c   = i * 512 + tid;
                int arr = c >> 10;            // 0..1
                int rem = c & 1023;
                int row = rem >> 3;
                int c16 = rem & 7;
                const __nv_bfloat16* g =
                    (arr ? Btlo : Bthi) + (size_t)row * K + k0 + c16 * 8;
                unsigned d = smbase +
                    (unsigned)((2 + arr) * TILE_E + row * GP + c16 * 8) * 2;
                cp16(d, g);
            }
            asm volatile("cp.async.commit_group;\n");
            // A: LDG.128 fp32 -> split -> STS.64 into Ahi/Alo tiles
            #pragma unroll
            for (int i = 0; i < 4; i++) {
                int c   = i * 512 + tid;      // 0..2047 float4s
                int row = c >> 4;             // 128 rows x 16 f4/row
                int c4  = c & 15;
                int gr  = m0 + row; if (gr >= M) gr = 0;
                float4 v = *(const float4*)&Af[(size_t)gr * K + k0 + c4 * 4];
                __nv_bfloat16 h0, l0, h1, l1, h2, l2, h3, l3;
                splitf(v.x, h0, l0); splitf(v.y, h1, l1);
                splitf(v.z, h2, l2); splitf(v.w, h3, l3);
                unsigned eo = (unsigned)(row * GP + c4 * 4) * 2;
                *(uint2*)((char*)sm + 0 * TILE_E * 2 + eo) =
                    make_uint2(pack2(h0, h1), pack2(h2, h3));
                *(uint2*)((char*)sm + 1 * TILE_E * 2 + eo) =
                    make_uint2(pack2(l0, l1), pack2(l2, l3));
            }
            asm volatile("cp.async.wait_group 0;\n");
        } else {
            // 4 arrays x 128 rows x 8 chunks = 4096, 8/thread
            const __nv_bfloat16* gsrc[4] = {Ahi, Alo, Bthi, Btlo};
            #pragma unroll
            for (int i = 0; i < 8; i++) {
                int c   = i * 512 + tid;
                int arr = c >> 10;
                int rem = c & 1023;
                int row = rem >> 3;
                int c16 = rem & 7;
                int gr;
                if (arr < 2) { gr = m0 + row; if (gr >= M) gr = 0; }
                else         { gr = row; }
                const __nv_bfloat16* g =
                    gsrc[arr] + (size_t)gr * K + k0 + c16 * 8;
                unsigned d = smbase +
                    (unsigned)(arr * TILE_E + row * GP + c16 * 8) * 2;
                cp16(d, g);
            }
            asm volatile("cp.async.commit_group;\n");
            asm volatile("cp.async.wait_group 0;\n");
        }
        __syncthreads();

        unsigned bAhi = smbase;
        unsigned bAlo = smbase + (unsigned)TILE_E * 2;
        unsigned bBhi = smbase + (unsigned)TILE_E * 4;
        unsigned bBlo = smbase + (unsigned)TILE_E * 6;

        #pragma unroll
        for (int k16 = 0; k16 < 4; k16++) {
            int kc = k16 * 16;
            unsigned bhi[8], blo[8];
            {
                int in0 = lj >> 1, h0 = lj & 1;
                unsigned off0 = (unsigned)((warpN * 32 + in0 * 8 + ri) * GP
                                           + kc + h0 * 8) * 2;
                unsigned off1 = (unsigned)((warpN * 32 + 16 + in0 * 8 + ri) * GP
                                           + kc + h0 * 8) * 2;
                ldsm4(bhi,     bBhi + off0);
                ldsm4(bhi + 4, bBhi + off1);
                ldsm4(blo,     bBlo + off0);
                ldsm4(blo + 4, bBlo + off1);
            }
            #pragma unroll
            for (int im = 0; im < 2; im++) {
                int r0 = warpM * 32 + im * 16;
                unsigned aoff = (unsigned)((r0 + (lj & 1) * 8 + ri) * GP
                                           + kc + (lj >> 1) * 8) * 2;
                unsigned ahi[4], alo[4];
                ldsm4(ahi, bAhi + aoff);
                ldsm4(alo, bAlo + aoff);
                #pragma unroll
                for (int in = 0; in < 4; in++) {
                    mma_bf16(acc[im][in], ahi, &bhi[in * 2]);
                    mma_bf16(acc[im][in], ahi, &blo[in * 2]);
                    mma_bf16(acc[im][in], alo, &bhi[in * 2]);
                }
            }
        }
        __syncthreads();
    }

    #pragma unroll
    for (int im = 0; im < 2; im++) {
        int r = m0 + warpM * 32 + im * 16 + (lane >> 2);
        #pragma unroll
        for (int in = 0; in < 4; in++) {
            int c = warpN * 32 + in * 8 + (lane & 3) * 2;
            if (r < M)
                *(__half2*)&C[(size_t)r * 128 + c] =
                    __floats2half2_rn(acc[im][in][0], acc[im][in][1]);
            if (r + 8 < M)
                *(__half2*)&C[(size_t)(r + 8) * 128 + c] =
                    __floats2half2_rn(acc[im][in][2], acc[im][in][3]);
        }
    }
}

// -------------------- aggregation (fp16 gather tables) ---------------------
__device__ __forceinline__ float4 agg_node_h(const __half* __restrict__ t,
                                             int d, int lane) {
    float dv = g_dinv[d];
    size_t ch = lane * 4;
    uint2 uv = *(const uint2*)(t + (size_t)d * C_HID + ch);
    float2 v0 = __half22float2(*(__half2*)&uv.x);
    float2 v1 = __half22float2(*(__half2*)&uv.y);
    float w = dv * dv;
    float4 acc = make_float4(w * v0.x, w * v0.y, w * v1.x, w * v1.y);
    int beg = g_rowstart[d], end = g_rowstart[d + 1];
    int i = beg;
    for (; i + 1 < end; i += 2) {
        int s0 = g_csr[i], s1 = g_csr[i + 1];
        float w0 = dv * g_dinv[s0];
        float w1 = dv * g_dinv[s1];
        uint2 a = __ldg((const uint2*)(t + (size_t)s0 * C_HID + ch));
        uint2 b = __ldg((const uint2*)(t + (size_t)s1 * C_HID + ch));
        float2 a0 = __half22float2(*(__half2*)&a.x);
        float2 a1 = __half22float2(*(__half2*)&a.y);
        float2 b0 = __half22float2(*(__half2*)&b.x);
        float2 b1 = __half22float2(*(__half2*)&b.y);
        acc.x += w0 * a0.x + w1 * b0.x;
        acc.y += w0 * a0.y + w1 * b0.y;
        acc.z += w0 * a1.x + w1 * b1.x;
        acc.w += w0 * a1.y + w1 * b1.y;
    }
    if (i < end) {
        int s0 = g_csr[i];
        float w0 = dv * g_dinv[s0];
        uint2 a = __ldg((const uint2*)(t + (size_t)s0 * C_HID + ch));
        float2 a0 = __half22float2(*(__half2*)&a.x);
        float2 a1 = __half22float2(*(__half2*)&a.y);
        acc.x += w0 * a0.x; acc.y += w0 * a0.y;
        acc.z += w0 * a1.x; acc.w += w0 * a1.y;
    }
    return acc;
}

// h = relu(A_hat t1 + b1) emitted as (hi, lo) bf16 pair for GEMM2.
__global__ void __launch_bounds__(256)
k_agg1(const float* __restrict__ b1) {
    int gw = (blockIdx.x * blockDim.x + threadIdx.x) >> 5;
    if (gw >= N_NODES) return;
    int lane = threadIdx.x & 31;
    float4 acc = agg_node_h(g_t1h, gw, lane);
    float4 bb = *(const float4*)&b1[lane * 4];
    acc.x = fmaxf(acc.x + bb.x, 0.f);
    acc.y = fmaxf(acc.y + bb.y, 0.f);
    acc.z = fmaxf(acc.z + bb.z, 0.f);
    acc.w = fmaxf(acc.w + bb.w, 0.f);
    __nv_bfloat16 h0, l0, h1, l1, h2, l2, h3, l3;
    splitf(acc.x, h0, l0); splitf(acc.y, h1, l1);
    splitf(acc.z, h2, l2); splitf(acc.w, h3, l3);
    size_t o = (size_t)gw * C_HID + lane * 4;
    *(uint2*)&g_hhi[o] = make_uint2(pack2(h0, h1), pack2(h2, h3));
    *(uint2*)&g_hlo[o] = make_uint2(pack2(l0, l1), pack2(l2, l3));
}

__global__ void __launch_bounds__(256)
k_agg2(const float* __restrict__ b_mu, const float* __restrict__ b_ls,
       float* __restrict__ out) {
    int gw = (blockIdx.x * blockDim.x + threadIdx.x) >> 5;
    if (gw >= N_NODES) return;
    int lane = threadIdx.x & 31;
    float4 acc = agg_node_h(g_t2h, gw, lane);
    int c = lane * 4;
    if (c < 64) {
        float4 bb = *(const float4*)&b_mu[c];
        acc.x += bb.x; acc.y += bb.y; acc.z += bb.z; acc.w += bb.w;
        *(float4*)&out[(size_t)gw * 64 + c] = acc;
    } else {
        float4 bb = *(const float4*)&b_ls[c - 64];
        acc.x += bb.x; acc.y += bb.y; acc.z += bb.z; acc.w += bb.w;
        *(float4*)&out[(size_t)N_NODES * 64 + (size_t)gw * 64 + (c - 64)] = acc;
    }
}

// -------------------- launch -----------------------------------------------
extern "C" void kernel_launch(void* const* d_in, const int* in_sizes, int n_in,
                              void* d_out, int out_size) {
    const float* x    = (const float*)d_in[0];
    const void*  ei   = d_in[1];
    const float* W1   = (const float*)d_in[2];
    const float* b1   = (const float*)d_in[3];
    const float* Wmu  = (const float*)d_in[4];
    const float* bmu  = (const float*)d_in[5];
    const float* Wls  = (const float*)d_in[6];
    const float* bls  = (const float*)d_in[7];
    float*       out  = (float*)d_out;

    (void)in_sizes; (void)n_in; (void)out_size;

    void *p_w1thi, *p_w1tlo, *p_wcthi, *p_wctlo;
    void *p_hhi, *p_hlo, *p_t1h, *p_t2h;
    cudaGetSymbolAddress(&p_w1thi, g_w1thi);
    cudaGetSymbolAddress(&p_w1tlo, g_w1tlo);
    cudaGetSymbolAddress(&p_wcthi, g_wcthi);
    cudaGetSymbolAddress(&p_wctlo, g_wctlo);
    cudaGetSymbolAddress(&p_hhi,   g_hhi);
    cudaGetSymbolAddress(&p_hlo,   g_hlo);
    cudaGetSymbolAddress(&p_t1h,   g_t1h);
    cudaGetSymbolAddress(&p_t2h,   g_t2h);

    cudaFuncSetAttribute(k_gemm<true>,
        cudaFuncAttributeMaxDynamicSharedMemorySize, SMEM_BYTES);
    cudaFuncSetAttribute(k_gemm<false>,
        cudaFuncAttributeMaxDynamicSharedMemorySize, SMEM_BYTES);

    int nblk = (N_NODES + 127) / 128;

    // weight prep (no graph dependency)
    k_detect <<<1, 1>>>((const unsigned int*)ei);
    k_splitw1<<<(C_IN * C_HID + 255) / 256, 256>>>(W1);
    k_packwt <<<(C_HID * C_HID + 255) / 256, 256>>>(Wmu, Wls);

    // GEMM1, fused fp32->bf16 split (ncu capture slot 4)
    k_gemm<true><<<nblk, 512, SMEM_BYTES>>>(
        x, nullptr, nullptr,
        (const __nv_bfloat16*)p_w1thi, (const __nv_bfloat16*)p_w1tlo,
        (__half*)p_t1h, N_NODES, C_IN);

    // graph preprocessing
    k_set_deg<<<(N_NODES + 255) / 256, 256>>>();
    k_count  <<<(N_EDGES + 255) / 256, 256>>>(ei);
    k_scan1  <<<NB1, 1024>>>();
    k_scan2  <<<1, 128>>>();
    k_scan3  <<<(N_NODES + 255) / 256, 256>>>();
    k_scatter<<<(N_EDGES + 255) / 256, 256>>>(ei);

    // layer 1 aggregate (emits split h)
    k_agg1<<<(N_NODES * 32 + 255) / 256, 256>>>(b1);

    // layers 2+3 fused (pre-split h path)
    k_gemm<false><<<nblk, 512, SMEM_BYTES>>>(
        nullptr,
        (const __nv_bfloat16*)p_hhi, (const __nv_bfloat16*)p_hlo,
        (const __nv_bfloat16*)p_wcthi, (const __nv_bfloat16*)p_wctlo,
        (__half*)p_t2h, N_NODES, C_HID);
    k_agg2<<<(N_NODES * 32 + 255) / 256, 256>>>(bmu, bls, out);
}

// round 16
// speedup vs baseline: 1.2596x; 1.0381x over previous
#include <cuda_runtime.h>
#include <cuda_bf16.h>
#include <cuda_fp16.h>
#include <cstdint>

// ---------------------------------------------------------------------------
// VariationalEncoder (3-layer GCN VGAE), N=100000, E=1600000, 512->128->{64,64}
// R16 (from R15 @ 335.9us, GEMM1 140.7us tensor=53%): whole-CTA stalls at the
// per-stage A-load chain are covered by only 2 co-resident CTAs. Halve the
// CTA tile: BM=64, 256 thr, 8 warps (warp tile unchanged 32x32) -> smem
// 55.3KB, regs<=64 -> 4 CTA/SM -> 4 staggered sync domains. B re-reads stay
// L2-resident. Everything else identical to R15.
// ---------------------------------------------------------------------------

#define N_NODES 100000
#define N_EDGES 1600000
#define C_IN    512
#define C_HID   128
#define NB1     ((N_NODES + 1023) / 1024)

// -------------------- device scratch ---------------------------------------
__device__ int    g_is64;
__device__ int    g_deg[N_NODES];
__device__ float  g_dinv[N_NODES];
__device__ int    g_rowstart[N_NODES + 1];
__device__ int    g_cursor[N_NODES];
__device__ int    g_bsum[NB1];
__device__ int    g_boff[NB1 + 1];
__device__ int    g_csr[N_EDGES];
__device__ __nv_bfloat16 g_w1thi[C_HID * C_IN];   // [n][k] transposed
__device__ __nv_bfloat16 g_w1tlo[C_HID * C_IN];
__device__ __nv_bfloat16 g_wcthi[C_HID * C_HID];  // [n][k], n = [mu|ls]
__device__ __nv_bfloat16 g_wctlo[C_HID * C_HID];
__device__ __nv_bfloat16 g_hhi[(size_t)N_NODES * C_HID];
__device__ __nv_bfloat16 g_hlo[(size_t)N_NODES * C_HID];
__device__ __half g_t1h[(size_t)N_NODES * C_HID];   // fp16 gather tables
__device__ __half g_t2h[(size_t)N_NODES * C_HID];

// -------------------- helpers ----------------------------------------------
__device__ __forceinline__ void splitf(float x, __nv_bfloat16& hi,
                                       __nv_bfloat16& lo) {
    hi = __float2bfloat16_rn(x);
    lo = __float2bfloat16_rn(x - __bfloat162float(hi));
}
__device__ __forceinline__ unsigned pack2(__nv_bfloat16 a, __nv_bfloat16 b) {
    return (unsigned)__bfloat16_as_ushort(a) |
           ((unsigned)__bfloat16_as_ushort(b) << 16);
}

// -------------------- dtype detection --------------------------------------
__global__ void k_detect(const unsigned int* __restrict__ w) {
    bool is64 = true;
    #pragma unroll
    for (int i = 0; i < 8; i++)
        if (w[2 * i + 1] != 0u) is64 = false;
    g_is64 = is64 ? 1 : 0;
}

__device__ __forceinline__ int edge_at(const void* __restrict__ ei,
                                       int row, int e) {
    if (g_is64)
        return (int)((const long long*)ei)[(size_t)row * N_EDGES + e];
    return ((const int*)ei)[(size_t)row * N_EDGES + e];
}

// -------------------- weight splits ----------------------------------------
__global__ void k_splitw1(const float* __restrict__ W1) {
    int i = blockIdx.x * blockDim.x + threadIdx.x;   // over 512*128
    if (i >= C_IN * C_HID) return;
    int k = i >> 7, n = i & 127;
    __nv_bfloat16 h, l;
    splitf(W1[i], h, l);
    g_w1thi[n * C_IN + k] = h;
    g_w1tlo[n * C_IN + k] = l;
}

__global__ void k_packwt(const float* __restrict__ Wmu,
                         const float* __restrict__ Wls) {
    int i = blockIdx.x * blockDim.x + threadIdx.x;   // over 128*128
    if (i >= C_HID * C_HID) return;
    int k = i >> 7, n = i & 127;
    float w = (n < 64) ? Wmu[k * 64 + n] : Wls[k * 64 + (n - 64)];
    __nv_bfloat16 h, l;
    splitf(w, h, l);
    g_wcthi[n * C_HID + k] = h;
    g_wctlo[n * C_HID + k] = l;
}

// -------------------- graph preprocessing ----------------------------------
__global__ void k_set_deg(void) {
    int i = blockIdx.x * blockDim.x + threadIdx.x;
    if (i < N_NODES) g_deg[i] = 1;
}

__global__ void k_count(const void* __restrict__ ei) {
    int e = blockIdx.x * blockDim.x + threadIdx.x;
    if (e < N_EDGES) {
        int d = edge_at(ei, 1, e);
        if (d >= 0 && d < N_NODES) atomicAdd(&g_deg[d], 1);
    }
}

__global__ void __launch_bounds__(1024) k_scan1(void) {
    int tid  = threadIdx.x;
    int idx  = blockIdx.x * 1024 + tid;
    int lane = tid & 31, wid = tid >> 5;
    int deg = (idx < N_NODES) ? g_deg[idx] : 1;
    int v   = (idx < N_NODES) ? (deg - 1) : 0;
    if (idx < N_NODES) g_dinv[idx] = rsqrtf((float)deg);
    int incl = v;
    #pragma unroll
    for (int off = 1; off < 32; off <<= 1) {
        int t = __shfl_up_sync(0xffffffffu, incl, off);
        if (lane >= off) incl += t;
    }
    __shared__ int wsum[32];
    if (lane == 31) wsum[wid] = incl;
    __syncthreads();
    if (wid == 0) {
        int s = wsum[lane];
        #pragma unroll
        for (int off = 1; off < 32; off <<= 1) {
            int t = __shfl_up_sync(0xffffffffu, s, off);
            if (lane >= off) s += t;
        }
        wsum[lane] = s;
    }
    __syncthreads();
    int woff = (wid > 0) ? wsum[wid - 1] : 0;
    int excl = woff + incl - v;
    if (idx < N_NODES) g_rowstart[idx] = excl;
    if (tid == 1023) g_bsum[blockIdx.x] = woff + incl;
}

__global__ void k_scan2(void) {
    __shared__ int s[128];
    int tid = threadIdx.x;
    int v = (tid < NB1) ? g_bsum[tid] : 0;
    s[tid] = v;
    __syncthreads();
    #pragma unroll
    for (int off = 1; off < 128; off <<= 1) {
        int t = (tid >= off) ? s[tid - off] : 0;
        __syncthreads();
        s[tid] += t;
        __syncthreads();
    }
    int incl = s[tid];
    if (tid < NB1) g_boff[tid] = incl - v;
    if (tid == NB1 - 1) g_boff[NB1] = incl;
}

__global__ void k_scan3(void) {
    int idx = blockIdx.x * blockDim.x + threadIdx.x;
    if (idx < N_NODES) {
        int r = g_rowstart[idx] + g_boff[idx >> 10];
        g_rowstart[idx] = r;
        g_cursor[idx]   = r;
    }
    if (idx == 0) g_rowstart[N_NODES] = g_boff[NB1];
}

__global__ void k_scatter(const void* __restrict__ ei) {
    int e = blockIdx.x * blockDim.x + threadIdx.x;
    if (e < N_EDGES) {
        int sidx = edge_at(ei, 0, e);
        int d    = edge_at(ei, 1, e);
        if (d >= 0 && d < N_NODES && sidx >= 0 && sidx < N_NODES) {
            int pos = atomicAdd(&g_cursor[d], 1);
            if (pos >= 0 && pos < N_EDGES) g_csr[pos] = sidx;
        }
    }
}

// -------------------- HMMA GEMM: BM=64, 4 CTA/SM, fused A-split ------------
// C[M,128] (fp16) = (Ahi+Alo)[M,K] @ (Bthi+Btlo)[128,K]^T  (3-term split)
// 256 thr (8 warps, 2x4), BK=64, single-buffer smem, ldmatrix.x4 frags.
#define GP       72                   // bf16 pitch (144 B, conflict-free LDSM)
#define TILE_EA  (64 * GP)            // A tile: 64 rows
#define TILE_EB  (128 * GP)           // B tile: 128 rows
#define SMEM_BYTES ((2 * TILE_EA + 2 * TILE_EB) * 2)   // 55296 B

__device__ __forceinline__ void mma_bf16(float* c, const unsigned* a,
                                         const unsigned* b) {
    asm volatile(
        "mma.sync.aligned.m16n8k16.row.col.f32.bf16.bf16.f32 "
        "{%0,%1,%2,%3}, {%4,%5,%6,%7}, {%8,%9}, {%0,%1,%2,%3};"
        : "+f"(c[0]), "+f"(c[1]), "+f"(c[2]), "+f"(c[3])
        : "r"(a[0]), "r"(a[1]), "r"(a[2]), "r"(a[3]), "r"(b[0]), "r"(b[1]));
}

__device__ __forceinline__ void ldsm4(unsigned* r, unsigned addr) {
    asm volatile(
        "ldmatrix.sync.aligned.m8n8.x4.shared.b16 {%0,%1,%2,%3}, [%4];"
        : "=r"(r[0]), "=r"(r[1]), "=r"(r[2]), "=r"(r[3]) : "r"(addr));
}

__device__ __forceinline__ void cp16(unsigned s, const void* g) {
    asm volatile("cp.async.cg.shared.global [%0], [%1], 16;\n"
                 :: "r"(s), "l"(g));
}

template <bool FUSEA>
__global__ void __launch_bounds__(256, 4)
k_gemm(const float* __restrict__ Af,             // fp32 A (FUSEA only)
       const __nv_bfloat16* __restrict__ Ahi,    // pre-split A (else)
       const __nv_bfloat16* __restrict__ Alo,
       const __nv_bfloat16* __restrict__ Bthi,   // [128][K]
       const __nv_bfloat16* __restrict__ Btlo,
       __half* __restrict__ C, int M, int K) {
    extern __shared__ __nv_bfloat16 sm[];
    unsigned smbase = (unsigned)__cvta_generic_to_shared(sm);

    int tid   = threadIdx.x;
    int lane  = tid & 31;
    int wid   = tid >> 5;
    int warpM = wid >> 2;            // 0..1 -> m * 32
    int warpN = wid & 3;             // 0..3 -> n * 32
    int m0    = blockIdx.x * 64;
    int S     = K / 64;

    float acc[2][4][4];
    #pragma unroll
    for (int i = 0; i < 2; i++)
        #pragma unroll
        for (int j = 0; j < 4; j++)
            #pragma unroll
            for (int r = 0; r < 4; r++) acc[i][j][r] = 0.f;

    int lj = lane >> 3;              // ldmatrix sub-tile index
    int ri = lane & 7;

    unsigned bAhi = smbase;
    unsigned bAlo = smbase + (unsigned)TILE_EA * 2;
    unsigned bBhi = smbase + (unsigned)TILE_EA * 4;
    unsigned bBlo = smbase + (unsigned)(TILE_EA * 4 + TILE_EB * 2);

    for (int s = 0; s < S; s++) {
        int k0 = s * 64;
        if (FUSEA) {
            // B tiles via cp.async: 2 arrays x 128 rows x 8 chunks = 2048
            #pragma unroll
            for (int i = 0; i < 8; i++) {
                int c   = i * 256 + tid;
                int arr = c >> 10;            // 0..1
                int rem = c & 1023;
                int row = rem >> 3;
                int c16 = rem & 7;
                const __nv_bfloat16* g =
                    (arr ? Btlo : Bthi) + (size_t)row * K + k0 + c16 * 8;
                unsigned d = (arr ? bBlo : bBhi) +
                    (unsigned)(row * GP + c16 * 8) * 2;
                cp16(d, g);
            }
            asm volatile("cp.async.commit_group;\n");
            // A: LDG.128 fp32 -> split -> STS.64; 64 rows x 16 f4 = 1024
            #pragma unroll
            for (int i = 0; i < 4; i++) {
                int c   = i * 256 + tid;      // 0..1023 float4s
                int row = c >> 4;             // 0..63
                int c4  = c & 15;
                int gr  = m0 + row; if (gr >= M) gr = 0;
                float4 v = *(const float4*)&Af[(size_t)gr * K + k0 + c4 * 4];
                __nv_bfloat16 h0, l0, h1, l1, h2, l2, h3, l3;
                splitf(v.x, h0, l0); splitf(v.y, h1, l1);
                splitf(v.z, h2, l2); splitf(v.w, h3, l3);
                unsigned eo = (unsigned)(row * GP + c4 * 4) * 2;
                *(uint2*)((char*)sm + eo) =
                    make_uint2(pack2(h0, h1), pack2(h2, h3));
                *(uint2*)((char*)sm + TILE_EA * 2 + eo) =
                    make_uint2(pack2(l0, l1), pack2(l2, l3));
            }
            asm volatile("cp.async.wait_group 0;\n");
        } else {
            // A: 2 x 64 x 8 = 1024 chunks; B: 2 x 128 x 8 = 2048; total 3072
            #pragma unroll
            for (int i = 0; i < 12; i++) {
                int c = i * 256 + tid;        // 0..3071
                const __nv_bfloat16* g;
                unsigned d;
                if (c < 1024) {
                    int arr = c >> 9;         // 0..1
                    int rem = c & 511;
                    int row = rem >> 3;
                    int c16 = rem & 7;
                    int gr  = m0 + row; if (gr >= M) gr = 0;
                    g = (arr ? Alo : Ahi) + (size_t)gr * K + k0 + c16 * 8;
                    d = (arr ? bAlo : bAhi) + (unsigned)(row * GP + c16 * 8) * 2;
                } else {
                    int cb  = c - 1024;
                    int arr = cb >> 10;       // 0..1
                    int rem = cb & 1023;
                    int row = rem >> 3;
                    int c16 = rem & 7;
                    g = (arr ? Btlo : Bthi) + (size_t)row * K + k0 + c16 * 8;
                    d = (arr ? bBlo : bBhi) + (unsigned)(row * GP + c16 * 8) * 2;
                }
                cp16(d, g);
            }
            asm volatile("cp.async.commit_group;\n");
            asm volatile("cp.async.wait_group 0;\n");
        }
        __syncthreads();

        #pragma unroll
        for (int k16 = 0; k16 < 4; k16++) {
            int kc = k16 * 16;
            unsigned bhi[8], blo[8];
            {
                int in0 = lj >> 1, h0 = lj & 1;
                unsigned off0 = (unsigned)((warpN * 32 + in0 * 8 + ri) * GP
                                           + kc + h0 * 8) * 2;
                unsigned off1 = (unsigned)((warpN * 32 + 16 + in0 * 8 + ri) * GP
                                           + kc + h0 * 8) * 2;
                ldsm4(bhi,     bBhi + off0);
                ldsm4(bhi + 4, bBhi + off1);
                ldsm4(blo,     bBlo + off0);
                ldsm4(blo + 4, bBlo + off1);
            }
            #pragma unroll
            for (int im = 0; im < 2; im++) {
                int r0 = warpM * 32 + im * 16;
                unsigned aoff = (unsigned)((r0 + (lj & 1) * 8 + ri) * GP
                                           + kc + (lj >> 1) * 8) * 2;
                unsigned ahi[4], alo[4];
                ldsm4(ahi, bAhi + aoff);
                ldsm4(alo, bAlo + aoff);
                #pragma unroll
                for (int in = 0; in < 4; in++) {
                    mma_bf16(acc[im][in], ahi, &bhi[in * 2]);
                    mma_bf16(acc[im][in], ahi, &blo[in * 2]);
                    mma_bf16(acc[im][in], alo, &bhi[in * 2]);
                }
            }
        }
        __syncthreads();
    }

    #pragma unroll
    for (int im = 0; im < 2; im++) {
        int r = m0 + warpM * 32 + im * 16 + (lane >> 2);
        #pragma unroll
        for (int in = 0; in < 4; in++) {
            int c = warpN * 32 + in * 8 + (lane & 3) * 2;
            if (r < M)
                *(__half2*)&C[(size_t)r * 128 + c] =
                    __floats2half2_rn(acc[im][in][0], acc[im][in][1]);
            if (r + 8 < M)
                *(__half2*)&C[(size_t)(r + 8) * 128 + c] =
                    __floats2half2_rn(acc[im][in][2], acc[im][in][3]);
        }
    }
}

// -------------------- aggregation (fp16 gather tables) ---------------------
__device__ __forceinline__ float4 agg_node_h(const __half* __restrict__ t,
                                             int d, int lane) {
    float dv = g_dinv[d];
    size_t ch = lane * 4;
    uint2 uv = *(const uint2*)(t + (size_t)d * C_HID + ch);
    float2 v0 = __half22float2(*(__half2*)&uv.x);
    float2 v1 = __half22float2(*(__half2*)&uv.y);
    float w = dv * dv;
    float4 acc = make_float4(w * v0.x, w * v0.y, w * v1.x, w * v1.y);
    int beg = g_rowstart[d], end = g_rowstart[d + 1];
    int i = beg;
    for (; i + 1 < end; i += 2) {
        int s0 = g_csr[i], s1 = g_csr[i + 1];
        float w0 = dv * g_dinv[s0];
        float w1 = dv * g_dinv[s1];
        uint2 a = __ldg((const uint2*)(t + (size_t)s0 * C_HID + ch));
        uint2 b = __ldg((const uint2*)(t + (size_t)s1 * C_HID + ch));
        float2 a0 = __half22float2(*(__half2*)&a.x);
        float2 a1 = __half22float2(*(__half2*)&a.y);
        float2 b0 = __half22float2(*(__half2*)&b.x);
        float2 b1 = __half22float2(*(__half2*)&b.y);
        acc.x += w0 * a0.x + w1 * b0.x;
        acc.y += w0 * a0.y + w1 * b0.y;
        acc.z += w0 * a1.x + w1 * b1.x;
        acc.w += w0 * a1.y + w1 * b1.y;
    }
    if (i < end) {
        int s0 = g_csr[i];
        float w0 = dv * g_dinv[s0];
        uint2 a = __ldg((const uint2*)(t + (size_t)s0 * C_HID + ch));
        float2 a0 = __half22float2(*(__half2*)&a.x);
        float2 a1 = __half22float2(*(__half2*)&a.y);
        acc.x += w0 * a0.x; acc.y += w0 * a0.y;
        acc.z += w0 * a1.x; acc.w += w0 * a1.y;
    }
    return acc;
}

// h = relu(A_hat t1 + b1) emitted as (hi, lo) bf16 pair for GEMM2.
__global__ void __launch_bounds__(256)
k_agg1(const float* __restrict__ b1) {
    int gw = (blockIdx.x * blockDim.x + threadIdx.x) >> 5;
    if (gw >= N_NODES) return;
    int lane = threadIdx.x & 31;
    float4 acc = agg_node_h(g_t1h, gw, lane);
    float4 bb = *(const float4*)&b1[lane * 4];
    acc.x = fmaxf(acc.x + bb.x, 0.f);
    acc.y = fmaxf(acc.y + bb.y, 0.f);
    acc.z = fmaxf(acc.z + bb.z, 0.f);
    acc.w = fmaxf(acc.w + bb.w, 0.f);
    __nv_bfloat16 h0, l0, h1, l1, h2, l2, h3, l3;
    splitf(acc.x, h0, l0); splitf(acc.y, h1, l1);
    splitf(acc.z, h2, l2); splitf(acc.w, h3, l3);
    size_t o = (size_t)gw * C_HID + lane * 4;
    *(uint2*)&g_hhi[o] = make_uint2(pack2(h0, h1), pack2(h2, h3));
    *(uint2*)&g_hlo[o] = make_uint2(pack2(l0, l1), pack2(l2, l3));
}

__global__ void __launch_bounds__(256)
k_agg2(const float* __restrict__ b_mu, const float* __restrict__ b_ls,
       float* __restrict__ out) {
    int gw = (blockIdx.x * blockDim.x + threadIdx.x) >> 5;
    if (gw >= N_NODES) return;
    int lane = threadIdx.x & 31;
    float4 acc = agg_node_h(g_t2h, gw, lane);
    int c = lane * 4;
    if (c < 64) {
        float4 bb = *(const float4*)&b_mu[c];
        acc.x += bb.x; acc.y += bb.y; acc.z += bb.z; acc.w += bb.w;
        *(float4*)&out[(size_t)gw * 64 + c] = acc;
    } else {
        float4 bb = *(const float4*)&b_ls[c - 64];
        acc.x += bb.x; acc.y += bb.y; acc.z += bb.z; acc.w += bb.w;
        *(float4*)&out[(size_t)N_NODES * 64 + (size_t)gw * 64 + (c - 64)] = acc;
    }
}

// -------------------- launch -----------------------------------------------
extern "C" void kernel_launch(void* const* d_in, const int* in_sizes, int n_in,
                              void* d_out, int out_size) {
    const float* x    = (const float*)d_in[0];
    const void*  ei   = d_in[1];
    const float* W1   = (const float*)d_in[2];
    const float* b1   = (const float*)d_in[3];
    const float* Wmu  = (const float*)d_in[4];
    const float* bmu  = (const float*)d_in[5];
    const float* Wls  = (const float*)d_in[6];
    const float* bls  = (const float*)d_in[7];
    float*       out  = (float*)d_out;

    (void)in_sizes; (void)n_in; (void)out_size;

    void *p_w1thi, *p_w1tlo, *p_wcthi, *p_wctlo;
    void *p_hhi, *p_hlo, *p_t1h, *p_t2h;
    cudaGetSymbolAddress(&p_w1thi, g_w1thi);
    cudaGetSymbolAddress(&p_w1tlo, g_w1tlo);
    cudaGetSymbolAddress(&p_wcthi, g_wcthi);
    cudaGetSymbolAddress(&p_wctlo, g_wctlo);
    cudaGetSymbolAddress(&p_hhi,   g_hhi);
    cudaGetSymbolAddress(&p_hlo,   g_hlo);
    cudaGetSymbolAddress(&p_t1h,   g_t1h);
    cudaGetSymbolAddress(&p_t2h,   g_t2h);

    cudaFuncSetAttribute(k_gemm<true>,
        cudaFuncAttributeMaxDynamicSharedMemorySize, SMEM_BYTES);
    cudaFuncSetAttribute(k_gemm<false>,
        cudaFuncAttributeMaxDynamicSharedMemorySize, SMEM_BYTES);

    int nblk = (N_NODES + 63) / 64;

    // weight prep (no graph dependency)
    k_detect <<<1, 1>>>((const unsigned int*)ei);
    k_splitw1<<<(C_IN * C_HID + 255) / 256, 256>>>(W1);
    k_packwt <<<(C_HID * C_HID + 255) / 256, 256>>>(Wmu, Wls);

    // GEMM1, fused fp32->bf16 split
    k_gemm<true><<<nblk, 256, SMEM_BYTES>>>(
        x, nullptr, nullptr,
        (const __nv_bfloat16*)p_w1thi, (const __nv_bfloat16*)p_w1tlo,
        (__half*)p_t1h, N_NODES, C_IN);

    // graph preprocessing
    k_set_deg<<<(N_NODES + 255) / 256, 256>>>();
    k_count  <<<(N_EDGES + 255) / 256, 256>>>(ei);
    k_scan1  <<<NB1, 1024>>>();
    k_scan2  <<<1, 128>>>();
    k_scan3  <<<(N_NODES + 255) / 256, 256>>>();
    k_scatter<<<(N_EDGES + 255) / 256, 256>>>(ei);

    // layer 1 aggregate (emits split h)
    k_agg1<<<(N_NODES * 32 + 255) / 256, 256>>>(b1);

    // layers 2+3 fused (pre-split h path)
    k_gemm<false><<<nblk, 256, SMEM_BYTES>>>(
        nullptr,
        (const __nv_bfloat16*)p_hhi, (const __nv_bfloat16*)p_hlo,
        (const __nv_bfloat16*)p_wcthi, (const __nv_bfloat16*)p_wctlo,
        (__half*)p_t2h, N_NODES, C_HID);
    k_agg2<<<(N_NODES * 32 + 255) / 256, 256>>>(bmu, bls, out);
}

// round 17
// speedup vs baseline: 1.2922x; 1.0259x over previous
#include <cuda_runtime.h>
#include <cuda_bf16.h>
#include <cuda_fp16.h>
#include <cstdint>

// ---------------------------------------------------------------------------
// VariationalEncoder (3-layer GCN VGAE), N=100000, E=1600000, 512->128->{64,64}
// R17 (from R16 @ 323.6us): kernels unchanged. Launch topology change only:
// graph-capture FORK -- preprocessing chain (detect/set_deg/count/scans/
// scatter, ~45us, depends only on edge_index) runs on a secondary captured
// stream concurrent with GEMM1 (128us, depends only on x/W1); join before
// agg1 which needs both. Event-edge pattern is capture-legal.
// ---------------------------------------------------------------------------

#define N_NODES 100000
#define N_EDGES 1600000
#define C_IN    512
#define C_HID   128
#define NB1     ((N_NODES + 1023) / 1024)

// -------------------- device scratch ---------------------------------------
__device__ int    g_is64;
__device__ int    g_deg[N_NODES];
__device__ float  g_dinv[N_NODES];
__device__ int    g_rowstart[N_NODES + 1];
__device__ int    g_cursor[N_NODES];
__device__ int    g_bsum[NB1];
__device__ int    g_boff[NB1 + 1];
__device__ int    g_csr[N_EDGES];
__device__ __nv_bfloat16 g_w1thi[C_HID * C_IN];   // [n][k] transposed
__device__ __nv_bfloat16 g_w1tlo[C_HID * C_IN];
__device__ __nv_bfloat16 g_wcthi[C_HID * C_HID];  // [n][k], n = [mu|ls]
__device__ __nv_bfloat16 g_wctlo[C_HID * C_HID];
__device__ __nv_bfloat16 g_hhi[(size_t)N_NODES * C_HID];
__device__ __nv_bfloat16 g_hlo[(size_t)N_NODES * C_HID];
__device__ __half g_t1h[(size_t)N_NODES * C_HID];   // fp16 gather tables
__device__ __half g_t2h[(size_t)N_NODES * C_HID];

// -------------------- helpers ----------------------------------------------
__device__ __forceinline__ void splitf(float x, __nv_bfloat16& hi,
                                       __nv_bfloat16& lo) {
    hi = __float2bfloat16_rn(x);
    lo = __float2bfloat16_rn(x - __bfloat162float(hi));
}
__device__ __forceinline__ unsigned pack2(__nv_bfloat16 a, __nv_bfloat16 b) {
    return (unsigned)__bfloat16_as_ushort(a) |
           ((unsigned)__bfloat16_as_ushort(b) << 16);
}

// -------------------- dtype detection --------------------------------------
__global__ void k_detect(const unsigned int* __restrict__ w) {
    bool is64 = true;
    #pragma unroll
    for (int i = 0; i < 8; i++)
        if (w[2 * i + 1] != 0u) is64 = false;
    g_is64 = is64 ? 1 : 0;
}

__device__ __forceinline__ int edge_at(const void* __restrict__ ei,
                                       int row, int e) {
    if (g_is64)
        return (int)((const long long*)ei)[(size_t)row * N_EDGES + e];
    return ((const int*)ei)[(size_t)row * N_EDGES + e];
}

// -------------------- weight splits ----------------------------------------
__global__ void k_splitw1(const float* __restrict__ W1) {
    int i = blockIdx.x * blockDim.x + threadIdx.x;   // over 512*128
    if (i >= C_IN * C_HID) return;
    int k = i >> 7, n = i & 127;
    __nv_bfloat16 h, l;
    splitf(W1[i], h, l);
    g_w1thi[n * C_IN + k] = h;
    g_w1tlo[n * C_IN + k] = l;
}

__global__ void k_packwt(const float* __restrict__ Wmu,
                         const float* __restrict__ Wls) {
    int i = blockIdx.x * blockDim.x + threadIdx.x;   // over 128*128
    if (i >= C_HID * C_HID) return;
    int k = i >> 7, n = i & 127;
    float w = (n < 64) ? Wmu[k * 64 + n] : Wls[k * 64 + (n - 64)];
    __nv_bfloat16 h, l;
    splitf(w, h, l);
    g_wcthi[n * C_HID + k] = h;
    g_wctlo[n * C_HID + k] = l;
}

// -------------------- graph preprocessing ----------------------------------
__global__ void k_set_deg(void) {
    int i = blockIdx.x * blockDim.x + threadIdx.x;
    if (i < N_NODES) g_deg[i] = 1;
}

__global__ void k_count(const void* __restrict__ ei) {
    int e = blockIdx.x * blockDim.x + threadIdx.x;
    if (e < N_EDGES) {
        int d = edge_at(ei, 1, e);
        if (d >= 0 && d < N_NODES) atomicAdd(&g_deg[d], 1);
    }
}

__global__ void __launch_bounds__(1024) k_scan1(void) {
    int tid  = threadIdx.x;
    int idx  = blockIdx.x * 1024 + tid;
    int lane = tid & 31, wid = tid >> 5;
    int deg = (idx < N_NODES) ? g_deg[idx] : 1;
    int v   = (idx < N_NODES) ? (deg - 1) : 0;
    if (idx < N_NODES) g_dinv[idx] = rsqrtf((float)deg);
    int incl = v;
    #pragma unroll
    for (int off = 1; off < 32; off <<= 1) {
        int t = __shfl_up_sync(0xffffffffu, incl, off);
        if (lane >= off) incl += t;
    }
    __shared__ int wsum[32];
    if (lane == 31) wsum[wid] = incl;
    __syncthreads();
    if (wid == 0) {
        int s = wsum[lane];
        #pragma unroll
        for (int off = 1; off < 32; off <<= 1) {
            int t = __shfl_up_sync(0xffffffffu, s, off);
            if (lane >= off) s += t;
        }
        wsum[lane] = s;
    }
    __syncthreads();
    int woff = (wid > 0) ? wsum[wid - 1] : 0;
    int excl = woff + incl - v;
    if (idx < N_NODES) g_rowstart[idx] = excl;
    if (tid == 1023) g_bsum[blockIdx.x] = woff + incl;
}

__global__ void k_scan2(void) {
    __shared__ int s[128];
    int tid = threadIdx.x;
    int v = (tid < NB1) ? g_bsum[tid] : 0;
    s[tid] = v;
    __syncthreads();
    #pragma unroll
    for (int off = 1; off < 128; off <<= 1) {
        int t = (tid >= off) ? s[tid - off] : 0;
        __syncthreads();
        s[tid] += t;
        __syncthreads();
    }
    int incl = s[tid];
    if (tid < NB1) g_boff[tid] = incl - v;
    if (tid == NB1 - 1) g_boff[NB1] = incl;
}

__global__ void k_scan3(void) {
    int idx = blockIdx.x * blockDim.x + threadIdx.x;
    if (idx < N_NODES) {
        int r = g_rowstart[idx] + g_boff[idx >> 10];
        g_rowstart[idx] = r;
        g_cursor[idx]   = r;
    }
    if (idx == 0) g_rowstart[N_NODES] = g_boff[NB1];
}

__global__ void k_scatter(const void* __restrict__ ei) {
    int e = blockIdx.x * blockDim.x + threadIdx.x;
    if (e < N_EDGES) {
        int sidx = edge_at(ei, 0, e);
        int d    = edge_at(ei, 1, e);
        if (d >= 0 && d < N_NODES && sidx >= 0 && sidx < N_NODES) {
            int pos = atomicAdd(&g_cursor[d], 1);
            if (pos >= 0 && pos < N_EDGES) g_csr[pos] = sidx;
        }
    }
}

// -------------------- HMMA GEMM: BM=64, 4 CTA/SM, fused A-split ------------
// C[M,128] (fp16) = (Ahi+Alo)[M,K] @ (Bthi+Btlo)[128,K]^T  (3-term split)
// 256 thr (8 warps, 2x4), BK=64, single-buffer smem, ldmatrix.x4 frags.
#define GP       72                   // bf16 pitch (144 B, conflict-free LDSM)
#define TILE_EA  (64 * GP)            // A tile: 64 rows
#define TILE_EB  (128 * GP)           // B tile: 128 rows
#define SMEM_BYTES ((2 * TILE_EA + 2 * TILE_EB) * 2)   // 55296 B

__device__ __forceinline__ void mma_bf16(float* c, const unsigned* a,
                                         const unsigned* b) {
    asm volatile(
        "mma.sync.aligned.m16n8k16.row.col.f32.bf16.bf16.f32 "
        "{%0,%1,%2,%3}, {%4,%5,%6,%7}, {%8,%9}, {%0,%1,%2,%3};"
        : "+f"(c[0]), "+f"(c[1]), "+f"(c[2]), "+f"(c[3])
        : "r"(a[0]), "r"(a[1]), "r"(a[2]), "r"(a[3]), "r"(b[0]), "r"(b[1]));
}

__device__ __forceinline__ void ldsm4(unsigned* r, unsigned addr) {
    asm volatile(
        "ldmatrix.sync.aligned.m8n8.x4.shared.b16 {%0,%1,%2,%3}, [%4];"
        : "=r"(r[0]), "=r"(r[1]), "=r"(r[2]), "=r"(r[3]) : "r"(addr));
}

__device__ __forceinline__ void cp16(unsigned s, const void* g) {
    asm volatile("cp.async.cg.shared.global [%0], [%1], 16;\n"
                 :: "r"(s), "l"(g));
}

template <bool FUSEA>
__global__ void __launch_bounds__(256, 4)
k_gemm(const float* __restrict__ Af,             // fp32 A (FUSEA only)
       const __nv_bfloat16* __restrict__ Ahi,    // pre-split A (else)
       const __nv_bfloat16* __restrict__ Alo,
       const __nv_bfloat16* __restrict__ Bthi,   // [128][K]
       const __nv_bfloat16* __restrict__ Btlo,
       __half* __restrict__ C, int M, int K) {
    extern __shared__ __nv_bfloat16 sm[];
    unsigned smbase = (unsigned)__cvta_generic_to_shared(sm);

    int tid   = threadIdx.x;
    int lane  = tid & 31;
    int wid   = tid >> 5;
    int warpM = wid >> 2;            // 0..1 -> m * 32
    int warpN = wid & 3;             // 0..3 -> n * 32
    int m0    = blockIdx.x * 64;
    int S     = K / 64;

    float acc[2][4][4];
    #pragma unroll
    for (int i = 0; i < 2; i++)
        #pragma unroll
        for (int j = 0; j < 4; j++)
            #pragma unroll
            for (int r = 0; r < 4; r++) acc[i][j][r] = 0.f;

    int lj = lane >> 3;              // ldmatrix sub-tile index
    int ri = lane & 7;

    unsigned bAhi = smbase;
    unsigned bAlo = smbase + (unsigned)TILE_EA * 2;
    unsigned bBhi = smbase + (unsigned)TILE_EA * 4;
    unsigned bBlo = smbase + (unsigned)(TILE_EA * 4 + TILE_EB * 2);

    for (int s = 0; s < S; s++) {
        int k0 = s * 64;
        if (FUSEA) {
            // B tiles via cp.async: 2 arrays x 128 rows x 8 chunks = 2048
            #pragma unroll
            for (int i = 0; i < 8; i++) {
                int c   = i * 256 + tid;
                int arr = c >> 10;            // 0..1
                int rem = c & 1023;
                int row = rem >> 3;
                int c16 = rem & 7;
                const __nv_bfloat16* g =
                    (arr ? Btlo : Bthi) + (size_t)row * K + k0 + c16 * 8;
                unsigned d = (arr ? bBlo : bBhi) +
                    (unsigned)(row * GP + c16 * 8) * 2;
                cp16(d, g);
            }
            asm volatile("cp.async.commit_group;\n");
            // A: LDG.128 fp32 -> split -> STS.64; 64 rows x 16 f4 = 1024
            #pragma unroll
            for (int i = 0; i < 4; i++) {
                int c   = i * 256 + tid;      // 0..1023 float4s
                int row = c >> 4;             // 0..63
                int c4  = c & 15;
                int gr  = m0 + row; if (gr >= M) gr = 0;
                float4 v = *(const float4*)&Af[(size_t)gr * K + k0 + c4 * 4];
                __nv_bfloat16 h0, l0, h1, l1, h2, l2, h3, l3;
                splitf(v.x, h0, l0); splitf(v.y, h1, l1);
                splitf(v.z, h2, l2); splitf(v.w, h3, l3);
                unsigned eo = (unsigned)(row * GP + c4 * 4) * 2;
                *(uint2*)((char*)sm + eo) =
                    make_uint2(pack2(h0, h1), pack2(h2, h3));
                *(uint2*)((char*)sm + TILE_EA * 2 + eo) =
                    make_uint2(pack2(l0, l1), pack2(l2, l3));
            }
            asm volatile("cp.async.wait_group 0;\n");
        } else {
            // A: 2 x 64 x 8 = 1024 chunks; B: 2 x 128 x 8 = 2048; total 3072
            #pragma unroll
            for (int i = 0; i < 12; i++) {
                int c = i * 256 + tid;        // 0..3071
                const __nv_bfloat16* g;
                unsigned d;
                if (c < 1024) {
                    int arr = c >> 9;         // 0..1
                    int rem = c & 511;
                    int row = rem >> 3;
                    int c16 = rem & 7;
                    int gr  = m0 + row; if (gr >= M) gr = 0;
                    g = (arr ? Alo : Ahi) + (size_t)gr * K + k0 + c16 * 8;
                    d = (arr ? bAlo : bAhi) + (unsigned)(row * GP + c16 * 8) * 2;
                } else {
                    int cb  = c - 1024;
                    int arr = cb >> 10;       // 0..1
                    int rem = cb & 1023;
                    int row = rem >> 3;
                    int c16 = rem & 7;
                    g = (arr ? Btlo : Bthi) + (size_t)row * K + k0 + c16 * 8;
                    d = (arr ? bBlo : bBhi) + (unsigned)(row * GP + c16 * 8) * 2;
                }
                cp16(d, g);
            }
            asm volatile("cp.async.commit_group;\n");
            asm volatile("cp.async.wait_group 0;\n");
        }
        __syncthreads();

        #pragma unroll
        for (int k16 = 0; k16 < 4; k16++) {
            int kc = k16 * 16;
            unsigned bhi[8], blo[8];
            {
                int in0 = lj >> 1, h0 = lj & 1;
                unsigned off0 = (unsigned)((warpN * 32 + in0 * 8 + ri) * GP
                                           + kc + h0 * 8) * 2;
                unsigned off1 = (unsigned)((warpN * 32 + 16 + in0 * 8 + ri) * GP
                                           + kc + h0 * 8) * 2;
                ldsm4(bhi,     bBhi + off0);
                ldsm4(bhi + 4, bBhi + off1);
                ldsm4(blo,     bBlo + off0);
                ldsm4(blo + 4, bBlo + off1);
            }
            #pragma unroll
            for (int im = 0; im < 2; im++) {
                int r0 = warpM * 32 + im * 16;
                unsigned aoff = (unsigned)((r0 + (lj & 1) * 8 + ri) * GP
                                           + kc + (lj >> 1) * 8) * 2;
                unsigned ahi[4], alo[4];
                ldsm4(ahi, bAhi + aoff);
                ldsm4(alo, bAlo + aoff);
                #pragma unroll
                for (int in = 0; in < 4; in++) {
                    mma_bf16(acc[im][in], ahi, &bhi[in * 2]);
                    mma_bf16(acc[im][in], ahi, &blo[in * 2]);
                    mma_bf16(acc[im][in], alo, &bhi[in * 2]);
                }
            }
        }
        __syncthreads();
    }

    #pragma unroll
    for (int im = 0; im < 2; im++) {
        int r = m0 + warpM * 32 + im * 16 + (lane >> 2);
        #pragma unroll
        for (int in = 0; in < 4; in++) {
            int c = warpN * 32 + in * 8 + (lane & 3) * 2;
            if (r < M)
                *(__half2*)&C[(size_t)r * 128 + c] =
                    __floats2half2_rn(acc[im][in][0], acc[im][in][1]);
            if (r + 8 < M)
                *(__half2*)&C[(size_t)(r + 8) * 128 + c] =
                    __floats2half2_rn(acc[im][in][2], acc[im][in][3]);
        }
    }
}

// -------------------- aggregation (fp16 gather tables) ---------------------
__device__ __forceinline__ float4 agg_node_h(const __half* __restrict__ t,
                                             int d, int lane) {
    float dv = g_dinv[d];
    size_t ch = lane * 4;
    uint2 uv = *(const uint2*)(t + (size_t)d * C_HID + ch);
    float2 v0 = __half22float2(*(__half2*)&uv.x);
    float2 v1 = __half22float2(*(__half2*)&uv.y);
    float w = dv * dv;
    float4 acc = make_float4(w * v0.x, w * v0.y, w * v1.x, w * v1.y);
    int beg = g_rowstart[d], end = g_rowstart[d + 1];
    int i = beg;
    for (; i + 1 < end; i += 2) {
        int s0 = g_csr[i], s1 = g_csr[i + 1];
        float w0 = dv * g_dinv[s0];
        float w1 = dv * g_dinv[s1];
        uint2 a = __ldg((const uint2*)(t + (size_t)s0 * C_HID + ch));
        uint2 b = __ldg((const uint2*)(t + (size_t)s1 * C_HID + ch));
        float2 a0 = __half22float2(*(__half2*)&a.x);
        float2 a1 = __half22float2(*(__half2*)&a.y);
        float2 b0 = __half22float2(*(__half2*)&b.x);
        float2 b1 = __half22float2(*(__half2*)&b.y);
        acc.x += w0 * a0.x + w1 * b0.x;
        acc.y += w0 * a0.y + w1 * b0.y;
        acc.z += w0 * a1.x + w1 * b1.x;
        acc.w += w0 * a1.y + w1 * b1.y;
    }
    if (i < end) {
        int s0 = g_csr[i];
        float w0 = dv * g_dinv[s0];
        uint2 a = __ldg((const uint2*)(t + (size_t)s0 * C_HID + ch));
        float2 a0 = __half22float2(*(__half2*)&a.x);
        float2 a1 = __half22float2(*(__half2*)&a.y);
        acc.x += w0 * a0.x; acc.y += w0 * a0.y;
        acc.z += w0 * a1.x; acc.w += w0 * a1.y;
    }
    return acc;
}

// h = relu(A_hat t1 + b1) emitted as (hi, lo) bf16 pair for GEMM2.
__global__ void __launch_bounds__(256)
k_agg1(const float* __restrict__ b1) {
    int gw = (blockIdx.x * blockDim.x + threadIdx.x) >> 5;
    if (gw >= N_NODES) return;
    int lane = threadIdx.x & 31;
    float4 acc = agg_node_h(g_t1h, gw, lane);
    float4 bb = *(const float4*)&b1[lane * 4];
    acc.x = fmaxf(acc.x + bb.x, 0.f);
    acc.y = fmaxf(acc.y + bb.y, 0.f);
    acc.z = fmaxf(acc.z + bb.z, 0.f);
    acc.w = fmaxf(acc.w + bb.w, 0.f);
    __nv_bfloat16 h0, l0, h1, l1, h2, l2, h3, l3;
    splitf(acc.x, h0, l0); splitf(acc.y, h1, l1);
    splitf(acc.z, h2, l2); splitf(acc.w, h3, l3);
    size_t o = (size_t)gw * C_HID + lane * 4;
    *(uint2*)&g_hhi[o] = make_uint2(pack2(h0, h1), pack2(h2, h3));
    *(uint2*)&g_hlo[o] = make_uint2(pack2(l0, l1), pack2(l2, l3));
}

__global__ void __launch_bounds__(256)
k_agg2(const float* __restrict__ b_mu, const float* __restrict__ b_ls,
       float* __restrict__ out) {
    int gw = (blockIdx.x * blockDim.x + threadIdx.x) >> 5;
    if (gw >= N_NODES) return;
    int lane = threadIdx.x & 31;
    float4 acc = agg_node_h(g_t2h, gw, lane);
    int c = lane * 4;
    if (c < 64) {
        float4 bb = *(const float4*)&b_mu[c];
        acc.x += bb.x; acc.y += bb.y; acc.z += bb.z; acc.w += bb.w;
        *(float4*)&out[(size_t)gw * 64 + c] = acc;
    } else {
        float4 bb = *(const float4*)&b_ls[c - 64];
        acc.x += bb.x; acc.y += bb.y; acc.z += bb.z; acc.w += bb.w;
        *(float4*)&out[(size_t)N_NODES * 64 + (size_t)gw * 64 + (c - 64)] = acc;
    }
}

// -------------------- launch -----------------------------------------------
extern "C" void kernel_launch(void* const* d_in, const int* in_sizes, int n_in,
                              void* d_out, int out_size) {
    const float* x    = (const float*)d_in[0];
    const void*  ei   = d_in[1];
    const float* W1   = (const float*)d_in[2];
    const float* b1   = (const float*)d_in[3];
    const float* Wmu  = (const float*)d_in[4];
    const float* bmu  = (const float*)d_in[5];
    const float* Wls  = (const float*)d_in[6];
    const float* bls  = (const float*)d_in[7];
    float*       out  = (float*)d_out;

    (void)in_sizes; (void)n_in; (void)out_size;

    void *p_w1thi, *p_w1tlo, *p_wcthi, *p_wctlo;
    void *p_hhi, *p_hlo, *p_t1h, *p_t2h;
    cudaGetSymbolAddress(&p_w1thi, g_w1thi);
    cudaGetSymbolAddress(&p_w1tlo, g_w1tlo);
    cudaGetSymbolAddress(&p_wcthi, g_wcthi);
    cudaGetSymbolAddress(&p_wctlo, g_wctlo);
    cudaGetSymbolAddress(&p_hhi,   g_hhi);
    cudaGetSymbolAddress(&p_hlo,   g_hlo);
    cudaGetSymbolAddress(&p_t1h,   g_t1h);
    cudaGetSymbolAddress(&p_t2h,   g_t2h);

    cudaFuncSetAttribute(k_gemm<true>,
        cudaFuncAttributeMaxDynamicSharedMemorySize, SMEM_BYTES);
    cudaFuncSetAttribute(k_gemm<false>,
        cudaFuncAttributeMaxDynamicSharedMemorySize, SMEM_BYTES);

    int nblk = (N_NODES + 63) / 64;

    // Fork a secondary captured stream for the edge-index preprocessing
    // chain (independent of GEMM1). Created per call, never destroyed
    // mid-capture (host-side objects only; no device allocations).
    cudaStream_t s2;
    cudaStreamCreateWithFlags(&s2, cudaStreamNonBlocking);
    cudaEvent_t eFork, eJoin;
    cudaEventCreateWithFlags(&eFork, cudaEventDisableTiming);
    cudaEventCreateWithFlags(&eJoin, cudaEventDisableTiming);

    cudaEventRecord(eFork, 0);
    cudaStreamWaitEvent(s2, eFork, 0);

    // --- secondary stream: edge preprocessing ---
    k_detect <<<1, 1, 0, s2>>>((const unsigned int*)ei);
    k_set_deg<<<(N_NODES + 255) / 256, 256, 0, s2>>>();
    k_count  <<<(N_EDGES + 255) / 256, 256, 0, s2>>>(ei);
    k_scan1  <<<NB1, 1024, 0, s2>>>();
    k_scan2  <<<1, 128, 0, s2>>>();
    k_scan3  <<<(N_NODES + 255) / 256, 256, 0, s2>>>();
    k_scatter<<<(N_EDGES + 255) / 256, 256, 0, s2>>>(ei);
    cudaEventRecord(eJoin, s2);

    // --- main stream: weight prep + GEMM1 (fused fp32->bf16 split) ---
    k_splitw1<<<(C_IN * C_HID + 255) / 256, 256>>>(W1);
    k_packwt <<<(C_HID * C_HID + 255) / 256, 256>>>(Wmu, Wls);
    k_gemm<true><<<nblk, 256, SMEM_BYTES>>>(
        x, nullptr, nullptr,
        (const __nv_bfloat16*)p_w1thi, (const __nv_bfloat16*)p_w1tlo,
        (__half*)p_t1h, N_NODES, C_IN);

    // join: agg1 needs both t1 (main) and CSR (s2)
    cudaStreamWaitEvent(0, eJoin, 0);

    k_agg1<<<(N_NODES * 32 + 255) / 256, 256>>>(b1);

    // layers 2+3 fused (pre-split h path)
    k_gemm<false><<<nblk, 256, SMEM_BYTES>>>(
        nullptr,
        (const __nv_bfloat16*)p_hhi, (const __nv_bfloat16*)p_hlo,
        (const __nv_bfloat16*)p_wcthi, (const __nv_bfloat16*)p_wctlo,
        (__half*)p_t2h, N_NODES, C_HID);
    k_agg2<<<(N_NODES * 32 + 255) / 256, 256>>>(bmu, bls, out);
}